// round 1
// baseline (speedup 1.0000x reference)
#include <cuda_runtime.h>
#include <cuda_bf16.h>

// APELoss: all-pairs ranking loss.
//   fg = logits[:F], bg = logits[F:]
//   mask(i,j) = bg_j > fg_i - 1         (rel_bg is provably implied)
//   d = 4*(x_j - fg_i),  h = d/2 = 2*x_j - 2*fg_i
//   sigmoid(d) = 0.5 + 0.5*tanh(h)
//   softplus(d) = max(d,0) - ln2 * log2(0.5*(1+|tanh(h)|))
// Per-fg accumulators (decomposed so the hot loop is just predicated adds):
//   sum_t, sum_relu(h), sum_lg2, count   (neg + pos contributions)
//   sum_t_tp, count_tp                   (tp contributions, sigmoid only)

#define MAXF    2048
#define THREADS 256
#define BG_TILE 512
#define NB_BG   294   // 150528 / 512; stride loop handles any shape anyway

__device__ float g_t[MAXF];
__device__ float g_relu[MAXF];
__device__ float g_lg[MAXF];
__device__ float g_ttp[MAXF];
__device__ int   g_cnt[MAXF];
__device__ int   g_ctp[MAXF];

__device__ __forceinline__ float tanh_approx(float x) {
    float r; asm("tanh.approx.f32 %0, %1;" : "=f"(r) : "f"(x)); return r;
}
__device__ __forceinline__ float lg2_approx(float x) {
    float r; asm("lg2.approx.f32 %0, %1;" : "=f"(r) : "f"(x)); return r;
}

__global__ void ape_zero_kernel(int F) {
    int i = blockIdx.x * blockDim.x + threadIdx.x;
    if (i < F) {
        g_t[i] = 0.f; g_relu[i] = 0.f; g_lg[i] = 0.f; g_ttp[i] = 0.f;
        g_cnt[i] = 0; g_ctp[i] = 0;
    }
}

// Each block: one (or more, strided) bg tile of BG_TILE elements x ALL fg rows.
// Thread t owns fg rows t, t+256, t+512, t+768 (register accumulators).
__global__ void __launch_bounds__(THREADS) ape_bg_kernel(
    const float* __restrict__ logits, int N, int F)
{
    const float* bg = logits + F;
    const int NBG = N - F;
    __shared__ float sh[BG_TILE];
    const int t = threadIdx.x;

    float f2[4];
#pragma unroll
    for (int r = 0; r < 4; r++) {
        int i = t + THREADS * r;
        f2[r] = (i < F) ? 2.0f * logits[i] : 3.0e38f;  // pad: mask never true
    }

    float at[4] = {0.f,0.f,0.f,0.f};
    float ar[4] = {0.f,0.f,0.f,0.f};
    float al[4] = {0.f,0.f,0.f,0.f};
    int   c [4] = {0,0,0,0};

    for (int base = blockIdx.x * BG_TILE; base < NBG; base += gridDim.x * BG_TILE) {
        int len = min(BG_TILE, NBG - base);
        __syncthreads();
        for (int k = t; k < len; k += THREADS) sh[k] = bg[base + k];
        __syncthreads();

#pragma unroll 4
        for (int j = 0; j < len; j++) {
            float b = sh[j];
            float b2 = b + b;
#pragma unroll
            for (int r = 0; r < 4; r++) {
                float h  = b2 - f2[r];
                float tt = tanh_approx(h);
                float u  = fmaf(0.5f, fabsf(tt), 0.5f);   // in (0.5, 1]
                float lg = lg2_approx(u);
                if (h > -2.0f) {
                    at[r] += tt;
                    al[r] += lg;
                    ar[r] += fmaxf(h, 0.0f);
                    c [r] += 1;
                }
            }
        }
    }

#pragma unroll
    for (int r = 0; r < 4; r++) {
        int i = t + THREADS * r;
        if (i < F && c[r] > 0) {
            atomicAdd(&g_t[i],    at[r]);
            atomicAdd(&g_relu[i], ar[r]);
            atomicAdd(&g_lg[i],   al[r]);
            atomicAdd(&g_cnt[i],  c[r]);
        }
    }
}

// fg x fg part: grid = nib * njb blocks; block handles 256 i-rows x one j-chunk.
__global__ void __launch_bounds__(THREADS) ape_fg_kernel(
    const float* __restrict__ logits, const float* __restrict__ ious, int F)
{
    const int nib = (F + THREADS - 1) / THREADS;
    const int ib  = blockIdx.x % nib;
    const int jb  = blockIdx.x / nib;
    const int njb = gridDim.x / nib;
    const int i   = ib * THREADS + threadIdx.x;

    __shared__ float shf[THREADS];
    __shared__ float shi[THREADS];

    const int jchunk = (F + njb - 1) / njb;
    const int j0 = jb * jchunk;
    const int j1 = min(F, j0 + jchunk);
    const int len = j1 - j0;

    for (int k = threadIdx.x; k < len; k += THREADS) {
        shf[k] = logits[j0 + k];
        shi[k] = ious[j0 + k];
    }
    __syncthreads();

    float fi2  = (i < F) ? 2.0f * logits[i] : 3.0e38f;
    float ioui = (i < F) ? ious[i] : 0.0f;

    float at = 0.f, ar = 0.f, al = 0.f, att = 0.f;
    int c = 0, ctp = 0;

    for (int k = 0; k < len; k++) {
        float h  = fmaf(2.0f, shf[k], -fi2);
        float tt = tanh_approx(h);
        float u  = fmaf(0.5f, fabsf(tt), 0.5f);
        float lg = lg2_approx(u);
        bool above = (h > -2.0f);
        bool pos   = (shi[k] < ioui);
        if (above) {
            if (pos) { at += tt; al += lg; ar += fmaxf(h, 0.0f); c++; }
            else     { att += tt; ctp++; }
        }
    }

    if (i < F) {
        if (c) {
            atomicAdd(&g_t[i],    at);
            atomicAdd(&g_relu[i], ar);
            atomicAdd(&g_lg[i],   al);
            atomicAdd(&g_cnt[i],  c);
        }
        if (ctp) {
            atomicAdd(&g_ttp[i], att);
            atomicAdd(&g_ctp[i], ctp);
        }
    }
}

__global__ void ape_fin_kernel(const float* __restrict__ ious, int F,
                               float* __restrict__ out)
{
    __shared__ float ssum[THREADS];
    __shared__ int   scnt[THREADS];
    const int t = threadIdx.x;
    float s = 0.f; int nv = 0;
    for (int i = t; i < F; i += THREADS) {
        int   cnt  = g_cnt[i];
        float sig  = fmaf(0.5f, g_t[i],   0.5f * (float)cnt);
        float tp   = fmaf(0.5f, g_ttp[i], 0.5f * (float)g_ctp[i]);
        float rank = sig + tp;
        float dist = fmaf(2.0f, g_relu[i], -0.69314718056f * g_lg[i]);
        if (cnt > 0) { s += dist * ious[i] / rank; nv++; }
    }
    ssum[t] = s; scnt[t] = nv;
    __syncthreads();
    for (int o = THREADS / 2; o > 0; o >>= 1) {
        if (t < o) { ssum[t] += ssum[t + o]; scnt[t] += scnt[t + o]; }
        __syncthreads();
    }
    if (t == 0) {
        int n = scnt[0] > 0 ? scnt[0] : 1;
        out[0] = ssum[0] / (float)n * 0.25f;   // / LAMB
    }
}

extern "C" void kernel_launch(void* const* d_in, const int* in_sizes, int n_in,
                              void* d_out, int out_size)
{
    const float* logits = (const float*)d_in[0];
    // d_in[1] = targets (unused: fg/bg split is positional in the reference)
    const float* ious   = (const float*)d_in[2];
    const int N = in_sizes[0];
    const int F = in_sizes[2];   // ious has length num_fg

    ape_zero_kernel<<<(F + THREADS - 1) / THREADS, THREADS>>>(F);

    ape_bg_kernel<<<NB_BG, THREADS>>>(logits, N, F);

    int nib = (F + THREADS - 1) / THREADS;   // 4 for F=1024
    int njb = 4;                              // j-chunks
    ape_fg_kernel<<<nib * njb, THREADS>>>(logits, ious, F);

    ape_fin_kernel<<<1, THREADS>>>(ious, F, (float*)d_out);
}

// round 2
// speedup vs baseline: 1.8431x; 1.8431x over previous
#include <cuda_runtime.h>
#include <cuda_bf16.h>

// APELoss via bucketed moment expansion.
//   For each fg i: masked bg set = { bg > fg_i - 1 } (rel_bg provably implied).
//   sigma(d), softplus(d) with d = 4*(bg - fg_i) are expanded per bg-bucket
//   (width 1/16) as 3rd-order Taylor around the bucket center, using
//   precomputed centered moments M0..M3. The single threshold-straddling
//   bucket is evaluated exactly from a bucket-sorted copy of bg.
//   fg x fg (1024^2) part is exact.
//
// Identities (t = tanh(d/2)):
//   sigmoid(d)  = 0.5 + 0.5*t
//   softplus(d) = max(d,0) - ln2 * log2(0.5*(1+|t|))
//   s' = s(1-s), s'' = s'(1-2s), s''' = s''(1-2s) - 2 s'^2

#define NB      256
#define BMIN    (-8.0f)
#define INVW    16.0f
#define WBUK    0.0625f
#define MAXN    160000
#define LN2     0.69314718056f

__device__ float4 g_mom[NB];     // M0, M1, M2, M3 per bucket
__device__ int    g_hist[NB];
__device__ int    g_start[NB];
__device__ int    g_cursor[NB];
__device__ float  g_sorted[MAXN];
__device__ float  g_sum;
__device__ int    g_nv;

__device__ __forceinline__ float tanh_approx(float x) {
    float r; asm("tanh.approx.f32 %0, %1;" : "=f"(r) : "f"(x)); return r;
}
__device__ __forceinline__ float lg2_approx(float x) {
    float r; asm("lg2.approx.f32 %0, %1;" : "=f"(r) : "f"(x)); return r;
}
__device__ __forceinline__ int bucket_of(float b) {
    int k = (int)floorf((b - BMIN) * INVW);
    return max(0, min(NB - 1, k));
}

// ---------------- K0: zero ----------------
__global__ void k0_zero() {
    int t = threadIdx.x;
    if (t < NB) { g_mom[t] = make_float4(0.f, 0.f, 0.f, 0.f); g_hist[t] = 0; }
    if (t == 0) { g_sum = 0.f; g_nv = 0; }
}

// ---------------- K1: moments + histogram over bg ----------------
__global__ void __launch_bounds__(256) k1_moments(const float* __restrict__ bg, int n) {
    __shared__ float sm[NB][4];
    __shared__ int   sh[NB];
    int t = threadIdx.x;
    for (int k = t; k < NB; k += blockDim.x) {
        sm[k][0] = sm[k][1] = sm[k][2] = sm[k][3] = 0.f; sh[k] = 0;
    }
    __syncthreads();
    for (int i = blockIdx.x * blockDim.x + t; i < n; i += gridDim.x * blockDim.x) {
        float b  = bg[i];
        int   k  = bucket_of(b);
        float db = b - (BMIN + ((float)k + 0.5f) * WBUK);
        float db2 = db * db;
        atomicAdd(&sm[k][0], 1.0f);
        atomicAdd(&sm[k][1], db);
        atomicAdd(&sm[k][2], db2);
        atomicAdd(&sm[k][3], db2 * db);
        atomicAdd(&sh[k], 1);
    }
    __syncthreads();
    float* gm = (float*)g_mom;
    for (int k = t; k < NB; k += blockDim.x) {
        if (sh[k]) {
            atomicAdd(&gm[4 * k + 0], sm[k][0]);
            atomicAdd(&gm[4 * k + 1], sm[k][1]);
            atomicAdd(&gm[4 * k + 2], sm[k][2]);
            atomicAdd(&gm[4 * k + 3], sm[k][3]);
            atomicAdd(&g_hist[k], sh[k]);
        }
    }
}

// ---------------- K2: exclusive scan of histogram (NB bins, 1 block) ----------------
__global__ void k2_scan() {
    __shared__ int s[NB];
    int t = threadIdx.x;
    int own = g_hist[t];
    s[t] = own;
    __syncthreads();
    for (int off = 1; off < NB; off <<= 1) {
        int v = (t >= off) ? s[t - off] : 0;
        __syncthreads();
        s[t] += v;
        __syncthreads();
    }
    int excl = s[t] - own;
    g_start[t]  = excl;
    g_cursor[t] = excl;
}

// ---------------- K3: scatter bg into bucket order ----------------
__global__ void __launch_bounds__(256) k3_scatter(const float* __restrict__ bg, int n) {
    for (int i = blockIdx.x * blockDim.x + threadIdx.x; i < n;
         i += gridDim.x * blockDim.x) {
        float b = bg[i];
        int   k = bucket_of(b);
        int   p = atomicAdd(&g_cursor[k], 1);
        g_sorted[p] = b;
    }
}

// ---------------- K4: per-fg main (one warp per fg) ----------------
__global__ void __launch_bounds__(256) k4_main(const float* __restrict__ logits,
                                               const float* __restrict__ ious, int F) {
    __shared__ float4 shm[NB];       // moments
    __shared__ float  sfg[1024];
    __shared__ float  sio[1024];
    int t = threadIdx.x;
    if (t < NB) shm[t] = g_mom[t];
    for (int j = t; j < F && j < 1024; j += blockDim.x) {
        sfg[j] = logits[j];
        sio[j] = ious[j];
    }
    __syncthreads();

    int warp = (blockIdx.x * blockDim.x + t) >> 5;
    int lane = t & 31;
    if (warp >= F) return;

    float f    = sfg[warp];
    float ioui = sio[warp];
    float c    = f + (-1.0f);            // fg + TH, matching reference rounding

    int kc;
    if (c < BMIN) kc = -1;
    else          kc = (int)floorf((c - BMIN) * INVW);   // may be >= NB -> no work

    float R = 0.f, D = 0.f, C = 0.f;

    // --- smooth buckets: Taylor-3 via moments ---
    for (int k = kc + 1 + lane; k < NB; k += 32) {
        float4 M = shm[k];
        if (M.x == 0.f) continue;
        float b0 = BMIN + ((float)k + 0.5f) * WBUK;
        float D0 = 4.0f * (b0 - f);
        float tt = tanh_approx(0.5f * D0);
        float s0 = fmaf(0.5f, tt, 0.5f);
        float s1 = s0 * (1.0f - s0);
        float s2 = s1 * (1.0f - 2.0f * s0);
        float s3 = s2 * (1.0f - 2.0f * s0) - 2.0f * s1 * s1;
        float u  = fmaf(0.5f, fabsf(tt), 0.5f);
        float p0 = fmaxf(D0, 0.0f) - LN2 * lg2_approx(u);
        // sum sigma over bucket
        float sr = M.x * s0 + 4.0f * M.y * s1 + 8.0f * M.z * s2
                 + 10.66666667f * M.w * s3;
        // sum softplus over bucket
        float sd = M.x * p0 + 4.0f * M.y * s0 + 8.0f * M.z * s1
                 + 10.66666667f * M.w * s2;
        R += sr; D += sd; C += M.x;
    }

    // --- boundary bucket: exact, masked per element ---
    if (kc >= 0 && kc < NB) {
        int st = g_start[kc];
        int n  = g_hist[kc];
        for (int m = st + lane; m < st + n; m += 32) {
            float b = g_sorted[m];
            if (b > c) {
                float h  = 2.0f * b - 2.0f * f;
                float tt = tanh_approx(h);
                float u  = fmaf(0.5f, fabsf(tt), 0.5f);
                R += fmaf(0.5f, tt, 0.5f);
                D += fmaf(2.0f, fmaxf(h, 0.0f), -LN2 * lg2_approx(u));
                C += 1.0f;
            }
        }
    }

    // --- fg x fg: exact ---
    for (int j = lane; j < F; j += 32) {
        float fj = sfg[j];
        if (fj > c) {                                  // above-mask (includes j==warp)
            float h  = 2.0f * fj - 2.0f * f;
            float tt = tanh_approx(h);
            float sg = fmaf(0.5f, tt, 0.5f);
            R += sg;                                   // fp or tp -> rank either way
            if (sio[j] < ioui) {                       // pos: also dist + count
                float u = fmaf(0.5f, fabsf(tt), 0.5f);
                D += fmaf(2.0f, fmaxf(h, 0.0f), -LN2 * lg2_approx(u));
                C += 1.0f;
            }
        }
    }

    // warp reduce
#pragma unroll
    for (int o = 16; o > 0; o >>= 1) {
        R += __shfl_xor_sync(0xffffffffu, R, o);
        D += __shfl_xor_sync(0xffffffffu, D, o);
        C += __shfl_xor_sync(0xffffffffu, C, o);
    }
    if (lane == 0) {
        if (C > 0.f) {
            atomicAdd(&g_sum, D * ioui / R);
            atomicAdd(&g_nv, 1);
        }
    }
}

// ---------------- K5: finalize ----------------
__global__ void k5_fin(float* __restrict__ out) {
    int n = g_nv;
    if (n < 1) n = 1;
    out[0] = g_sum * 0.25f / (float)n;    // LOSS_WEIGHT * sum / n_valid / LAMB
}

extern "C" void kernel_launch(void* const* d_in, const int* in_sizes, int n_in,
                              void* d_out, int out_size)
{
    const float* logits = (const float*)d_in[0];
    // d_in[1] = targets (unused: fg/bg split is positional)
    const float* ious   = (const float*)d_in[2];
    const int N = in_sizes[0];
    const int F = in_sizes[2];
    const float* bg = logits + F;
    const int NBG = N - F;

    k0_zero<<<1, 256>>>();
    k1_moments<<<96, 256>>>(bg, NBG);
    k2_scan<<<1, NB>>>();
    k3_scatter<<<148, 256>>>(bg, NBG);
    k4_main<<<(F * 32 + 255) / 256, 256>>>(logits, ious, F);
    k5_fin<<<1, 1>>>((float*)d_out);
}

// round 3
// speedup vs baseline: 2.5656x; 1.3920x over previous
#include <cuda_runtime.h>
#include <cuda_bf16.h>

// APELoss via bucketed moment expansion (see R2 comments).
// R3: block-aggregated scatter (1 global atomic per bucket per block),
//     scan folded into scatter blocks, finalize folded into main kernel.

#define NB      256
#define BMIN    (-8.0f)
#define INVW    16.0f
#define WBUK    0.0625f
#define MAXN    160000
#define LN2     0.69314718056f

#define SCAT_TPB 256
#define SCAT_E   4    // elements per thread per block (one tile per block)

__device__ float4 g_mom[NB];     // M0, M1, M2, M3 per bucket
__device__ int    g_hist[NB];
__device__ int    g_start[NB];
__device__ int    g_cursor[NB];  // per-bucket block-offset cursor (aggregated)
__device__ float  g_sorted[MAXN];
__device__ float  g_sum;
__device__ int    g_nv;
__device__ unsigned int g_done;

__device__ __forceinline__ float tanh_approx(float x) {
    float r; asm("tanh.approx.f32 %0, %1;" : "=f"(r) : "f"(x)); return r;
}
__device__ __forceinline__ float lg2_approx(float x) {
    float r; asm("lg2.approx.f32 %0, %1;" : "=f"(r) : "f"(x)); return r;
}
__device__ __forceinline__ int bucket_of(float b) {
    int k = (int)floorf((b - BMIN) * INVW);
    return max(0, min(NB - 1, k));
}

// ---------------- K0: zero ----------------
__global__ void k0_zero() {
    int t = threadIdx.x;
    if (t < NB) {
        g_mom[t] = make_float4(0.f, 0.f, 0.f, 0.f);
        g_hist[t] = 0; g_cursor[t] = 0;
    }
    if (t == 0) { g_sum = 0.f; g_nv = 0; g_done = 0u; }
}

// ---------------- K1: moments + histogram over bg ----------------
__global__ void __launch_bounds__(256) k1_moments(const float* __restrict__ bg, int n) {
    __shared__ float sm[NB][4];
    __shared__ int   sh[NB];
    int t = threadIdx.x;
    sm[t][0] = sm[t][1] = sm[t][2] = sm[t][3] = 0.f; sh[t] = 0;
    __syncthreads();
    for (int i = blockIdx.x * blockDim.x + t; i < n; i += gridDim.x * blockDim.x) {
        float b  = bg[i];
        int   k  = bucket_of(b);
        float db = b - (BMIN + ((float)k + 0.5f) * WBUK);
        float db2 = db * db;
        atomicAdd(&sm[k][1], db);
        atomicAdd(&sm[k][2], db2);
        atomicAdd(&sm[k][3], db2 * db);
        atomicAdd(&sh[k], 1);
    }
    __syncthreads();
    float* gm = (float*)g_mom;
    if (sh[t]) {
        atomicAdd(&gm[4 * t + 0], (float)sh[t]);
        atomicAdd(&gm[4 * t + 1], sm[t][1]);
        atomicAdd(&gm[4 * t + 2], sm[t][2]);
        atomicAdd(&gm[4 * t + 3], sm[t][3]);
        atomicAdd(&g_hist[t], sh[t]);
    }
}

// ---------------- K3: aggregated scatter (scan computed per block) ----------------
__global__ void __launch_bounds__(SCAT_TPB) k3_scatter(const float* __restrict__ bg, int n) {
    __shared__ int lhist[NB];
    __shared__ int sscan[NB];
    __shared__ int lbase[NB];
    int t = threadIdx.x;
    lhist[t] = 0;
    __syncthreads();

    float v[SCAT_E]; int bk[SCAT_E]; int rk[SCAT_E];
    int base = blockIdx.x * SCAT_TPB * SCAT_E;
#pragma unroll
    for (int e = 0; e < SCAT_E; e++) {
        int i = base + e * SCAT_TPB + t;
        if (i < n) {
            v[e]  = bg[i];
            bk[e] = bucket_of(v[e]);
            rk[e] = atomicAdd(&lhist[bk[e]], 1);
        } else bk[e] = -1;
    }
    __syncthreads();

    // exclusive scan of global histogram (redundant per block, cheap)
    int h = g_hist[t];
    sscan[t] = h;
    __syncthreads();
#pragma unroll
    for (int off = 1; off < NB; off <<= 1) {
        int x = (t >= off) ? sscan[t - off] : 0;
        __syncthreads();
        sscan[t] += x;
        __syncthreads();
    }
    int start = sscan[t] - h;
    if (blockIdx.x == 0) g_start[t] = start;     // publish for k4

    int cnt = lhist[t];
    lbase[t] = start + (cnt ? atomicAdd(&g_cursor[t], cnt) : 0);
    __syncthreads();

#pragma unroll
    for (int e = 0; e < SCAT_E; e++)
        if (bk[e] >= 0) g_sorted[lbase[bk[e]] + rk[e]] = v[e];
}

// ---------------- K4: per-fg main (one warp per fg) + fused finalize ----------------
__global__ void __launch_bounds__(256) k4_main(const float* __restrict__ logits,
                                               const float* __restrict__ ious, int F,
                                               float* __restrict__ out) {
    __shared__ float4 shm[NB];
    __shared__ float  sfg[1024];
    __shared__ float  sio[1024];
    int t = threadIdx.x;
    if (t < NB) shm[t] = g_mom[t];
    for (int j = t; j < F && j < 1024; j += blockDim.x) {
        sfg[j] = logits[j];
        sio[j] = ious[j];
    }
    __syncthreads();

    int warp = (blockIdx.x * blockDim.x + t) >> 5;
    int lane = t & 31;

    if (warp < F) {
        float f    = sfg[warp];
        float ioui = sio[warp];
        float c    = f + (-1.0f);            // fg + TH

        int kc;
        if (c < BMIN) kc = -1;
        else          kc = (int)floorf((c - BMIN) * INVW);

        float R = 0.f, D = 0.f, C = 0.f;

        // smooth buckets: Taylor-3 via moments
        for (int k = kc + 1 + lane; k < NB; k += 32) {
            float4 M = shm[k];
            if (M.x == 0.f) continue;
            float b0 = BMIN + ((float)k + 0.5f) * WBUK;
            float D0 = 4.0f * (b0 - f);
            float tt = tanh_approx(0.5f * D0);
            float s0 = fmaf(0.5f, tt, 0.5f);
            float s1 = s0 * (1.0f - s0);
            float s2 = s1 * (1.0f - 2.0f * s0);
            float s3 = s2 * (1.0f - 2.0f * s0) - 2.0f * s1 * s1;
            float u  = fmaf(0.5f, fabsf(tt), 0.5f);
            float p0 = fmaxf(D0, 0.0f) - LN2 * lg2_approx(u);
            R += M.x * s0 + 4.0f * M.y * s1 + 8.0f * M.z * s2
               + 10.66666667f * M.w * s3;
            D += M.x * p0 + 4.0f * M.y * s0 + 8.0f * M.z * s1
               + 10.66666667f * M.w * s2;
            C += M.x;
        }

        // boundary bucket: exact
        if (kc >= 0 && kc < NB) {
            int st = g_start[kc];
            int nb = g_hist[kc];
            for (int m = st + lane; m < st + nb; m += 32) {
                float b = g_sorted[m];
                if (b > c) {
                    float h  = 2.0f * b - 2.0f * f;
                    float tt = tanh_approx(h);
                    float u  = fmaf(0.5f, fabsf(tt), 0.5f);
                    R += fmaf(0.5f, tt, 0.5f);
                    D += fmaf(2.0f, fmaxf(h, 0.0f), -LN2 * lg2_approx(u));
                    C += 1.0f;
                }
            }
        }

        // fg x fg: exact
        for (int j = lane; j < F; j += 32) {
            float fj = sfg[j];
            if (fj > c) {
                float h  = 2.0f * fj - 2.0f * f;
                float tt = tanh_approx(h);
                R += fmaf(0.5f, tt, 0.5f);
                if (sio[j] < ioui) {
                    float u = fmaf(0.5f, fabsf(tt), 0.5f);
                    D += fmaf(2.0f, fmaxf(h, 0.0f), -LN2 * lg2_approx(u));
                    C += 1.0f;
                }
            }
        }

#pragma unroll
        for (int o = 16; o > 0; o >>= 1) {
            R += __shfl_xor_sync(0xffffffffu, R, o);
            D += __shfl_xor_sync(0xffffffffu, D, o);
            C += __shfl_xor_sync(0xffffffffu, C, o);
        }
        if (lane == 0 && C > 0.f) {
            atomicAdd(&g_sum, D * ioui / R);
            atomicAdd(&g_nv, 1);
        }
    }

    // fused finalize: last block to finish writes the scalar
    __syncthreads();
    if (t == 0) {
        __threadfence();
        unsigned int d = atomicAdd(&g_done, 1u);
        if (d == gridDim.x - 1) {
            float s = atomicAdd(&g_sum, 0.0f);   // atomic read (L2-coherent)
            int   n = atomicAdd(&g_nv, 0);
            if (n < 1) n = 1;
            out[0] = s * 0.25f / (float)n;       // / LAMB
        }
    }
}

extern "C" void kernel_launch(void* const* d_in, const int* in_sizes, int n_in,
                              void* d_out, int out_size)
{
    const float* logits = (const float*)d_in[0];
    // d_in[1] = targets (unused: fg/bg split is positional)
    const float* ious   = (const float*)d_in[2];
    const int N = in_sizes[0];
    const int F = in_sizes[2];
    const float* bg = logits + F;
    const int NBG = N - F;

    k0_zero<<<1, 256>>>();
    k1_moments<<<96, 256>>>(bg, NBG);
    int nscat = (NBG + SCAT_TPB * SCAT_E - 1) / (SCAT_TPB * SCAT_E);
    k3_scatter<<<nscat, SCAT_TPB>>>(bg, NBG);
    k4_main<<<(F * 32 + 255) / 256, 256>>>(logits, ious, F, (float*)d_out);
}

// round 4
// speedup vs baseline: 3.9303x; 1.5319x over previous
#include <cuda_runtime.h>
#include <cuda_bf16.h>

// APELoss via bucketed moment expansion.
// R4: k4 reorganized as one BLOCK (128 thr) per fg row -> 4x parallelism,
//     4x shorter serial path. Rest unchanged from R3.

#define NB      256
#define BMIN    (-8.0f)
#define INVW    16.0f
#define WBUK    0.0625f
#define MAXN    160000
#define LN2     0.69314718056f
#define MAXF    2048

#define SCAT_TPB 256
#define SCAT_E   4

#define K4_TPB  128

__device__ float4 g_mom[NB];
__device__ int    g_hist[NB];
__device__ int    g_start[NB];
__device__ int    g_cursor[NB];
__device__ float  g_sorted[MAXN];
__device__ float  g_sum;
__device__ int    g_nv;
__device__ unsigned int g_done;

__device__ __forceinline__ float tanh_approx(float x) {
    float r; asm("tanh.approx.f32 %0, %1;" : "=f"(r) : "f"(x)); return r;
}
__device__ __forceinline__ float lg2_approx(float x) {
    float r; asm("lg2.approx.f32 %0, %1;" : "=f"(r) : "f"(x)); return r;
}
__device__ __forceinline__ int bucket_of(float b) {
    int k = (int)floorf((b - BMIN) * INVW);
    return max(0, min(NB - 1, k));
}

// ---------------- K0: zero ----------------
__global__ void k0_zero() {
    int t = threadIdx.x;
    if (t < NB) {
        g_mom[t] = make_float4(0.f, 0.f, 0.f, 0.f);
        g_hist[t] = 0; g_cursor[t] = 0;
    }
    if (t == 0) { g_sum = 0.f; g_nv = 0; g_done = 0u; }
}

// ---------------- K1: moments + histogram over bg ----------------
__global__ void __launch_bounds__(256) k1_moments(const float* __restrict__ bg, int n) {
    __shared__ float sm[NB][4];
    __shared__ int   sh[NB];
    int t = threadIdx.x;
    sm[t][0] = sm[t][1] = sm[t][2] = sm[t][3] = 0.f; sh[t] = 0;
    __syncthreads();
    for (int i = blockIdx.x * blockDim.x + t; i < n; i += gridDim.x * blockDim.x) {
        float b  = bg[i];
        int   k  = bucket_of(b);
        float db = b - (BMIN + ((float)k + 0.5f) * WBUK);
        float db2 = db * db;
        atomicAdd(&sm[k][1], db);
        atomicAdd(&sm[k][2], db2);
        atomicAdd(&sm[k][3], db2 * db);
        atomicAdd(&sh[k], 1);
    }
    __syncthreads();
    float* gm = (float*)g_mom;
    if (sh[t]) {
        atomicAdd(&gm[4 * t + 0], (float)sh[t]);
        atomicAdd(&gm[4 * t + 1], sm[t][1]);
        atomicAdd(&gm[4 * t + 2], sm[t][2]);
        atomicAdd(&gm[4 * t + 3], sm[t][3]);
        atomicAdd(&g_hist[t], sh[t]);
    }
}

// ---------------- K3: aggregated scatter ----------------
__global__ void __launch_bounds__(SCAT_TPB) k3_scatter(const float* __restrict__ bg, int n) {
    __shared__ int lhist[NB];
    __shared__ int sscan[NB];
    __shared__ int lbase[NB];
    int t = threadIdx.x;
    lhist[t] = 0;
    __syncthreads();

    float v[SCAT_E]; int bk[SCAT_E]; int rk[SCAT_E];
    int base = blockIdx.x * SCAT_TPB * SCAT_E;
#pragma unroll
    for (int e = 0; e < SCAT_E; e++) {
        int i = base + e * SCAT_TPB + t;
        if (i < n) {
            v[e]  = bg[i];
            bk[e] = bucket_of(v[e]);
            rk[e] = atomicAdd(&lhist[bk[e]], 1);
        } else bk[e] = -1;
    }
    __syncthreads();

    int h = g_hist[t];
    sscan[t] = h;
    __syncthreads();
#pragma unroll
    for (int off = 1; off < NB; off <<= 1) {
        int x = (t >= off) ? sscan[t - off] : 0;
        __syncthreads();
        sscan[t] += x;
        __syncthreads();
    }
    int start = sscan[t] - h;
    if (blockIdx.x == 0) g_start[t] = start;

    int cnt = lhist[t];
    lbase[t] = start + (cnt ? atomicAdd(&g_cursor[t], cnt) : 0);
    __syncthreads();

#pragma unroll
    for (int e = 0; e < SCAT_E; e++)
        if (bk[e] >= 0) g_sorted[lbase[bk[e]] + rk[e]] = v[e];
}

// ---------------- K4: one block per fg + fused finalize ----------------
__global__ void __launch_bounds__(K4_TPB) k4_main(const float* __restrict__ logits,
                                                  const float* __restrict__ ious, int F,
                                                  float* __restrict__ out) {
    __shared__ float4 shm[NB];
    __shared__ float  sfg[MAXF];
    __shared__ float  sio[MAXF];
    __shared__ float  red[3][K4_TPB / 32];
    const int t = threadIdx.x;
    const int i = blockIdx.x;          // fg index

#pragma unroll
    for (int k = t; k < NB; k += K4_TPB) shm[k] = g_mom[k];
    for (int j = t; j < F; j += K4_TPB) {
        sfg[j] = logits[j];
        sio[j] = ious[j];
    }
    __syncthreads();

    float R = 0.f, D = 0.f, C = 0.f;
    float ioui = 0.f;
    bool active = (i < F);

    if (active) {
        float f = sfg[i];
        ioui    = sio[i];
        float c = f + (-1.0f);                    // fg + TH

        int kc;
        if (c < BMIN) kc = -1;
        else          kc = (int)floorf((c - BMIN) * INVW);

        // smooth buckets: Taylor-3 via moments
        for (int k = kc + 1 + t; k < NB; k += K4_TPB) {
            float4 M = shm[k];
            if (M.x == 0.f) continue;
            float b0 = BMIN + ((float)k + 0.5f) * WBUK;
            float D0 = 4.0f * (b0 - f);
            float tt = tanh_approx(0.5f * D0);
            float s0 = fmaf(0.5f, tt, 0.5f);
            float s1 = s0 * (1.0f - s0);
            float s2 = s1 * (1.0f - 2.0f * s0);
            float s3 = s2 * (1.0f - 2.0f * s0) - 2.0f * s1 * s1;
            float u  = fmaf(0.5f, fabsf(tt), 0.5f);
            float p0 = fmaxf(D0, 0.0f) - LN2 * lg2_approx(u);
            R += M.x * s0 + 4.0f * M.y * s1 + 8.0f * M.z * s2
               + 10.66666667f * M.w * s3;
            D += M.x * p0 + 4.0f * M.y * s0 + 8.0f * M.z * s1
               + 10.66666667f * M.w * s2;
            C += M.x;
        }

        // boundary bucket: exact
        if (kc >= 0 && kc < NB) {
            int st = g_start[kc];
            int nb = g_hist[kc];
            for (int m = st + t; m < st + nb; m += K4_TPB) {
                float b = g_sorted[m];
                if (b > c) {
                    float h  = 2.0f * b - 2.0f * f;
                    float tt = tanh_approx(h);
                    float u  = fmaf(0.5f, fabsf(tt), 0.5f);
                    R += fmaf(0.5f, tt, 0.5f);
                    D += fmaf(2.0f, fmaxf(h, 0.0f), -LN2 * lg2_approx(u));
                    C += 1.0f;
                }
            }
        }

        // fg x fg: exact
        for (int j = t; j < F; j += K4_TPB) {
            float fj = sfg[j];
            if (fj > c) {
                float h  = 2.0f * fj - 2.0f * f;
                float tt = tanh_approx(h);
                R += fmaf(0.5f, tt, 0.5f);
                if (sio[j] < ioui) {
                    float u = fmaf(0.5f, fabsf(tt), 0.5f);
                    D += fmaf(2.0f, fmaxf(h, 0.0f), -LN2 * lg2_approx(u));
                    C += 1.0f;
                }
            }
        }
    }

    // block reduce R, D, C
#pragma unroll
    for (int o = 16; o > 0; o >>= 1) {
        R += __shfl_xor_sync(0xffffffffu, R, o);
        D += __shfl_xor_sync(0xffffffffu, D, o);
        C += __shfl_xor_sync(0xffffffffu, C, o);
    }
    int warp = t >> 5, lane = t & 31;
    if (lane == 0) { red[0][warp] = R; red[1][warp] = D; red[2][warp] = C; }
    __syncthreads();
    if (t == 0) {
        float Rt = 0.f, Dt = 0.f, Ct = 0.f;
#pragma unroll
        for (int w = 0; w < K4_TPB / 32; w++) {
            Rt += red[0][w]; Dt += red[1][w]; Ct += red[2][w];
        }
        if (active && Ct > 0.f) {
            atomicAdd(&g_sum, Dt * ioui / Rt);
            atomicAdd(&g_nv, 1);
        }
        __threadfence();
        unsigned int d = atomicAdd(&g_done, 1u);
        if (d == gridDim.x - 1) {
            float s = atomicAdd(&g_sum, 0.0f);
            int   n = atomicAdd(&g_nv, 0);
            if (n < 1) n = 1;
            out[0] = s * 0.25f / (float)n;    // / LAMB
        }
    }
}

extern "C" void kernel_launch(void* const* d_in, const int* in_sizes, int n_in,
                              void* d_out, int out_size)
{
    const float* logits = (const float*)d_in[0];
    // d_in[1] = targets (unused: fg/bg split is positional)
    const float* ious   = (const float*)d_in[2];
    const int N = in_sizes[0];
    const int F = in_sizes[2];
    const float* bg = logits + F;
    const int NBG = N - F;

    k0_zero<<<1, 256>>>();
    k1_moments<<<96, 256>>>(bg, NBG);
    int nscat = (NBG + SCAT_TPB * SCAT_E - 1) / (SCAT_TPB * SCAT_E);
    k3_scatter<<<nscat, SCAT_TPB>>>(bg, NBG);
    k4_main<<<F, K4_TPB>>>(logits, ious, F, (float*)d_out);
}